// round 1
// baseline (speedup 1.0000x reference)
#include <cuda_runtime.h>
#include <cstdint>

#define BATCH 2
#define SEQ   2048
#define DIM   1024
#define NH    16
#define HDIM  64
#define MTOT  (BATCH * SEQ)   // 4096

// Scratch (allocation-free): Q, K, V, attention-output, all [MTOT, DIM] fp32
__device__ float g_Q[(size_t)MTOT * DIM];
__device__ float g_K[(size_t)MTOT * DIM];
__device__ float g_V[(size_t)MTOT * DIM];
__device__ float g_O[(size_t)MTOT * DIM];

// ---------------------------------------------------------------------------
// SGEMM with bias:  C[M,N] = A[M,K] @ W[N,K]^T + bias[N]
// BM=BN=128, BK=16, 8x8 microtile, 256 threads
// ---------------------------------------------------------------------------
#define BM 128
#define BN 128
#define BK 16
#define TM 8
#define TN 8

__global__ __launch_bounds__(256)
void sgemm_bias(const float* __restrict__ A, const float* __restrict__ W,
                const float* __restrict__ bias, float* __restrict__ C,
                int Mdim, int Ndim, int Kdim)
{
    __shared__ float As[BK][BM];
    __shared__ float Ws[BK][BN];

    const int tid  = threadIdx.x;
    const int brow = blockIdx.y;   // M tile
    const int bcol = blockIdx.x;   // N tile

    const float* Ap = A + (size_t)brow * BM * Kdim;
    const float* Wp = W + (size_t)bcol * BN * Kdim;

    // global->smem load mapping: each thread loads one float4 per tile
    const int lrow = tid >> 2;          // 0..63  -> covers 64 rows? (need 128)
    // 128 rows x 16 cols = 2048 floats = 256 threads * 8 floats = 2 float4 each
    const int lr0 = tid >> 2;           // row for first float4 (0..63)
    const int lc  = (tid & 3) * 4;      // k-offset 0,4,8,12
    (void)lrow;

    const int trow = (tid / 16) * TM;   // 0..120
    const int tcol = (tid % 16) * TN;   // 0..120

    float acc[TM][TN];
    #pragma unroll
    for (int i = 0; i < TM; i++)
        #pragma unroll
        for (int j = 0; j < TN; j++) acc[i][j] = 0.f;

    for (int k0 = 0; k0 < Kdim; k0 += BK) {
        // each thread loads 2 float4 from A and 2 from W (rows lr0 and lr0+64)
        float4 a0 = *(const float4*)(Ap + (size_t)lr0        * Kdim + k0 + lc);
        float4 a1 = *(const float4*)(Ap + (size_t)(lr0 + 64) * Kdim + k0 + lc);
        float4 w0 = *(const float4*)(Wp + (size_t)lr0        * Kdim + k0 + lc);
        float4 w1 = *(const float4*)(Wp + (size_t)(lr0 + 64) * Kdim + k0 + lc);

        __syncthreads();   // previous tile fully consumed

        // store transposed: As[k][m]
        As[lc + 0][lr0] = a0.x;  As[lc + 1][lr0] = a0.y;
        As[lc + 2][lr0] = a0.z;  As[lc + 3][lr0] = a0.w;
        As[lc + 0][lr0 + 64] = a1.x;  As[lc + 1][lr0 + 64] = a1.y;
        As[lc + 2][lr0 + 64] = a1.z;  As[lc + 3][lr0 + 64] = a1.w;
        Ws[lc + 0][lr0] = w0.x;  Ws[lc + 1][lr0] = w0.y;
        Ws[lc + 2][lr0] = w0.z;  Ws[lc + 3][lr0] = w0.w;
        Ws[lc + 0][lr0 + 64] = w1.x;  Ws[lc + 1][lr0 + 64] = w1.y;
        Ws[lc + 2][lr0 + 64] = w1.z;  Ws[lc + 3][lr0 + 64] = w1.w;

        __syncthreads();

        #pragma unroll
        for (int kk = 0; kk < BK; kk++) {
            float a[TM], b[TN];
            *(float4*)&a[0] = *(const float4*)&As[kk][trow];
            *(float4*)&a[4] = *(const float4*)&As[kk][trow + 4];
            *(float4*)&b[0] = *(const float4*)&Ws[kk][tcol];
            *(float4*)&b[4] = *(const float4*)&Ws[kk][tcol + 4];
            #pragma unroll
            for (int i = 0; i < TM; i++)
                #pragma unroll
                for (int j = 0; j < TN; j++)
                    acc[i][j] = fmaf(a[i], b[j], acc[i][j]);
        }
    }

    // epilogue: add bias, write
    const int crow0 = brow * BM + trow;
    const int ccol0 = bcol * BN + tcol;
    #pragma unroll
    for (int i = 0; i < TM; i++) {
        float* Crow = C + (size_t)(crow0 + i) * Ndim + ccol0;
        #pragma unroll
        for (int j = 0; j < TN; j += 4) {
            float4 o;
            o.x = acc[i][j + 0] + bias[ccol0 + j + 0];
            o.y = acc[i][j + 1] + bias[ccol0 + j + 1];
            o.z = acc[i][j + 2] + bias[ccol0 + j + 2];
            o.w = acc[i][j + 3] + bias[ccol0 + j + 3];
            *(float4*)(Crow + j) = o;
        }
    }
}

// ---------------------------------------------------------------------------
// Causal flash attention, fp32.
// Grid: (SEQ/128, BATCH*NH). Block: 128 threads, one query row per thread.
// Key tiles of 64 rows in smem. q-row + output accumulator in registers.
// smem: Ks[64][64] + Vs[64][64] + Ss[128][65]  = 66048 bytes (dynamic)
// ---------------------------------------------------------------------------
#define ATTN_SMEM ((64 * 64 + 64 * 64 + 128 * 65) * 4)

__global__ __launch_bounds__(128)
void attn_kernel(const float* __restrict__ Q, const float* __restrict__ K,
                 const float* __restrict__ V, float* __restrict__ O)
{
    extern __shared__ float sm[];
    float* Ks = sm;                 // [64][64]
    float* Vs = sm + 64 * 64;       // [64][64]
    float* Ss = sm + 2 * 64 * 64;   // [128][65]

    const int tid   = threadIdx.x;
    const int qtile = blockIdx.x;
    const int bh    = blockIdx.y;
    const int b     = bh >> 4;
    const int h     = bh & 15;

    const int sq = qtile * 128 + tid;
    const size_t rowm = (size_t)(b * SEQ + sq) * DIM + h * HDIM;

    __align__(16) float q[HDIM];
    __align__(16) float acc[HDIM];
    #pragma unroll
    for (int i = 0; i < 16; i++)
        ((float4*)q)[i] = ((const float4*)(Q + rowm))[i];
    #pragma unroll
    for (int d = 0; d < HDIM; d++) acc[d] = 0.f;

    float mi = -1e30f, li = 0.f;

    const float* Kbase = K + (size_t)b * SEQ * DIM + h * HDIM;
    const float* Vbase = V + (size_t)b * SEQ * DIM + h * HDIM;

    const int njt = 2 * qtile + 2;              // causal: key tiles 0..2*qtile+1
    const int t   = tid >> 1;                    // load row
    const int off = (tid & 1) * 32;              // half-row offset (floats)

    for (int j = 0; j < njt; j++) {
        const float4* kg = (const float4*)(Kbase + (size_t)(j * 64 + t) * DIM + off);
        const float4* vg = (const float4*)(Vbase + (size_t)(j * 64 + t) * DIM + off);
        float4* kd = (float4*)(Ks + t * 64 + off);
        float4* vd = (float4*)(Vs + t * 64 + off);

        __syncthreads();   // previous tile fully consumed
        #pragma unroll
        for (int i = 0; i < 8; i++) { kd[i] = kg[i]; vd[i] = vg[i]; }
        __syncthreads();

        // --- scores: s = (q . K_t) / 8, causal mask, track tile max ---
        float tmax = -1e30f;
        const int kidx0 = j * 64;
        #pragma unroll 4
        for (int t2 = 0; t2 < 64; t2++) {
            const float4* kr = (const float4*)(Ks + t2 * 64);
            float s0 = 0.f, s1 = 0.f, s2 = 0.f, s3 = 0.f;
            #pragma unroll
            for (int d = 0; d < 16; d++) {
                float4 k4 = kr[d];
                s0 = fmaf(q[4 * d + 0], k4.x, s0);
                s1 = fmaf(q[4 * d + 1], k4.y, s1);
                s2 = fmaf(q[4 * d + 2], k4.z, s2);
                s3 = fmaf(q[4 * d + 3], k4.w, s3);
            }
            float sc = ((s0 + s1) + (s2 + s3)) * 0.125f;
            if (kidx0 + t2 > sq) sc = -1e30f;
            tmax = fmaxf(tmax, sc);
            Ss[tid * 65 + t2] = sc;
        }

        // --- online softmax update ---
        const float mnew = fmaxf(mi, tmax);
        const float corr = __expf(mi - mnew);
        li *= corr;
        #pragma unroll
        for (int d = 0; d < HDIM; d++) acc[d] *= corr;

        #pragma unroll 2
        for (int t2 = 0; t2 < 64; t2++) {
            const float p = __expf(Ss[tid * 65 + t2] - mnew);
            li += p;
            const float4* vr = (const float4*)(Vs + t2 * 64);
            #pragma unroll
            for (int d = 0; d < 16; d++) {
                float4 v4 = vr[d];
                acc[4 * d + 0] = fmaf(p, v4.x, acc[4 * d + 0]);
                acc[4 * d + 1] = fmaf(p, v4.y, acc[4 * d + 1]);
                acc[4 * d + 2] = fmaf(p, v4.z, acc[4 * d + 2]);
                acc[4 * d + 3] = fmaf(p, v4.w, acc[4 * d + 3]);
            }
        }
        mi = mnew;
    }

    const float inv = 1.f / li;
    float* Op = O + rowm;
    #pragma unroll
    for (int d = 0; d < HDIM; d += 4) {
        float4 o4 = make_float4(acc[d] * inv, acc[d + 1] * inv,
                                acc[d + 2] * inv, acc[d + 3] * inv);
        *(float4*)(Op + d) = o4;
    }
}

// ---------------------------------------------------------------------------
// Launch
// ---------------------------------------------------------------------------
extern "C" void kernel_launch(void* const* d_in, const int* in_sizes, int n_in,
                              void* d_out, int out_size)
{
    const float* X  = (const float*)d_in[0];
    const float* Wq = (const float*)d_in[1];
    const float* bq = (const float*)d_in[2];
    const float* Wk = (const float*)d_in[3];
    const float* bk = (const float*)d_in[4];
    const float* Wv = (const float*)d_in[5];
    const float* bv = (const float*)d_in[6];
    const float* Wo = (const float*)d_in[7];
    const float* bo = (const float*)d_in[8];
    float* out = (float*)d_out;

    float *Q, *K, *V, *O;
    cudaGetSymbolAddress((void**)&Q, g_Q);
    cudaGetSymbolAddress((void**)&K, g_K);
    cudaGetSymbolAddress((void**)&V, g_V);
    cudaGetSymbolAddress((void**)&O, g_O);

    dim3 ggrid(DIM / BN, MTOT / BM);   // (8, 32)

    sgemm_bias<<<ggrid, 256>>>(X, Wq, bq, Q, MTOT, DIM, DIM);
    sgemm_bias<<<ggrid, 256>>>(X, Wk, bk, K, MTOT, DIM, DIM);
    sgemm_bias<<<ggrid, 256>>>(X, Wv, bv, V, MTOT, DIM, DIM);

    cudaFuncSetAttribute(attn_kernel,
                         cudaFuncAttributeMaxDynamicSharedMemorySize, ATTN_SMEM);
    attn_kernel<<<dim3(SEQ / 128, BATCH * NH), 128, ATTN_SMEM>>>(Q, K, V, O);

    sgemm_bias<<<ggrid, 256>>>(O, Wo, bo, out, MTOT, DIM, DIM);
}

// round 3
// speedup vs baseline: 1.2995x; 1.2995x over previous
#include <cuda_runtime.h>
#include <cuda_bf16.h>
#include <cstdint>

#define BATCH 2
#define SEQ   2048
#define DIM   1024
#define NH    16
#define HDIM  64
#define MTOT  (BATCH * SEQ)   // 4096

// ---------------------------------------------------------------------------
// Scratch (allocation-free __device__ globals)
// ---------------------------------------------------------------------------
__device__ float g_Q[(size_t)MTOT * DIM];
__device__ float g_K[(size_t)MTOT * DIM];
__device__ float g_V[(size_t)MTOT * DIM];
__device__ float g_O[(size_t)MTOT * DIM];

__device__ __align__(16) __nv_bfloat16 g_Xhi[(size_t)MTOT * DIM];
__device__ __align__(16) __nv_bfloat16 g_Xlo[(size_t)MTOT * DIM];
__device__ __align__(16) __nv_bfloat16 g_Ohi[(size_t)MTOT * DIM];
__device__ __align__(16) __nv_bfloat16 g_Olo[(size_t)MTOT * DIM];
__device__ __align__(16) __nv_bfloat16 g_Wqhi[(size_t)DIM * DIM];
__device__ __align__(16) __nv_bfloat16 g_Wqlo[(size_t)DIM * DIM];
__device__ __align__(16) __nv_bfloat16 g_Wkhi[(size_t)DIM * DIM];
__device__ __align__(16) __nv_bfloat16 g_Wklo[(size_t)DIM * DIM];
__device__ __align__(16) __nv_bfloat16 g_Wvhi[(size_t)DIM * DIM];
__device__ __align__(16) __nv_bfloat16 g_Wvlo[(size_t)DIM * DIM];
__device__ __align__(16) __nv_bfloat16 g_Wohi[(size_t)DIM * DIM];
__device__ __align__(16) __nv_bfloat16 g_Wolo[(size_t)DIM * DIM];

// ---------------------------------------------------------------------------
// PTX helpers (arch-neutral: sm_80-era instructions only)
// ---------------------------------------------------------------------------
__device__ __forceinline__ uint32_t smem_u32(const void* p) {
    uint32_t a;
    asm("{ .reg .u64 t; cvta.to.shared.u64 t, %1; cvt.u32.u64 %0, t; }"
        : "=r"(a) : "l"(p));
    return a;
}

__device__ __forceinline__ void cp16(uint32_t dst, const void* src) {
    asm volatile("cp.async.cg.shared.global [%0], [%1], 16;" :: "r"(dst), "l"(src));
}
__device__ __forceinline__ void cp_commit() {
    asm volatile("cp.async.commit_group;" ::: "memory");
}
__device__ __forceinline__ void cp_wait2() {
    asm volatile("cp.async.wait_group 2;" ::: "memory");
}
__device__ __forceinline__ void cp_wait0() {
    asm volatile("cp.async.wait_group 0;" ::: "memory");
}

__device__ __forceinline__ void ldsm4(uint32_t* r, uint32_t addr) {
    asm volatile("ldmatrix.sync.aligned.m8n8.x4.shared.b16 {%0,%1,%2,%3}, [%4];"
        : "=r"(r[0]), "=r"(r[1]), "=r"(r[2]), "=r"(r[3]) : "r"(addr));
}

__device__ __forceinline__ void mma16816(float* d, const uint32_t* a, const uint32_t* b) {
    asm volatile("mma.sync.aligned.m16n8k16.row.col.f32.bf16.bf16.f32 "
        "{%0,%1,%2,%3}, {%4,%5,%6,%7}, {%8,%9}, {%0,%1,%2,%3};"
        : "+f"(d[0]), "+f"(d[1]), "+f"(d[2]), "+f"(d[3])
        : "r"(a[0]), "r"(a[1]), "r"(a[2]), "r"(a[3]), "r"(b[0]), "r"(b[1]));
}

// ---------------------------------------------------------------------------
// hi/lo bf16 split:  x = hi + lo
// ---------------------------------------------------------------------------
__global__ __launch_bounds__(256)
void split_kernel(const float4* __restrict__ x, __nv_bfloat162* __restrict__ hi,
                  __nv_bfloat162* __restrict__ lo, int n4)
{
    int i = blockIdx.x * 256 + threadIdx.x;
    if (i >= n4) return;
    float4 v = x[i];
    __nv_bfloat16 h0 = __float2bfloat16_rn(v.x);
    __nv_bfloat16 h1 = __float2bfloat16_rn(v.y);
    __nv_bfloat16 h2 = __float2bfloat16_rn(v.z);
    __nv_bfloat16 h3 = __float2bfloat16_rn(v.w);
    __nv_bfloat16 l0 = __float2bfloat16_rn(v.x - __bfloat162float(h0));
    __nv_bfloat16 l1 = __float2bfloat16_rn(v.y - __bfloat162float(h1));
    __nv_bfloat16 l2 = __float2bfloat16_rn(v.z - __bfloat162float(h2));
    __nv_bfloat16 l3 = __float2bfloat16_rn(v.w - __bfloat162float(h3));
    hi[2 * i]     = __nv_bfloat162(h0, h1);
    hi[2 * i + 1] = __nv_bfloat162(h2, h3);
    lo[2 * i]     = __nv_bfloat162(l0, l1);
    lo[2 * i + 1] = __nv_bfloat162(l2, l3);
}

// ---------------------------------------------------------------------------
// bf16 split-GEMM via mma.sync:
//   C[M,1024] = Ahi@Whi^T + Alo@Whi^T + Ahi@Wlo^T + bias
// Folded K' = 3*1024 = 3072, chunks of BK=32, 4-stage cp.async pipeline.
// CTA tile 128x128, 8 warps (2x4), warp tile 64x32. grid (8, M/128).
// smem rows padded to 80B -> conflict-free ldmatrix & cp.async stores.
// ---------------------------------------------------------------------------
#define PADB 80
#define ATILE_B (128 * PADB)                 // 10240
#define STAGE_B (2 * ATILE_B)                // A + W = 20480
#define NSTAGE 4
#define GEMM_SMEM (NSTAGE * STAGE_B)         // 81920
#define NCHUNK 96                            // 3072 / 32

__device__ __forceinline__ void load_chunk(uint32_t sA, uint32_t sW,
    const __nv_bfloat16* __restrict__ A, const __nv_bfloat16* __restrict__ W,
    int k0, int tid)
{
    const int r = tid >> 2;          // 0..63
    const int q = tid & 3;           // 16B quarter of a 64B row-chunk
    const uint32_t doff = (uint32_t)q * 16;
    const int goff = k0 + q * 8;
    cp16(sA + (uint32_t)r * PADB + doff,        A + (size_t)r * DIM + goff);
    cp16(sA + (uint32_t)(r + 64) * PADB + doff, A + (size_t)(r + 64) * DIM + goff);
    cp16(sW + (uint32_t)r * PADB + doff,        W + (size_t)r * DIM + goff);
    cp16(sW + (uint32_t)(r + 64) * PADB + doff, W + (size_t)(r + 64) * DIM + goff);
    cp_commit();
}

__global__ __launch_bounds__(256)
void gemm_tc(const __nv_bfloat16* __restrict__ Ahi, const __nv_bfloat16* __restrict__ Alo,
             const __nv_bfloat16* __restrict__ Whi, const __nv_bfloat16* __restrict__ Wlo,
             const float* __restrict__ bias, float* __restrict__ C)
{
    extern __shared__ char smr[];
    const uint32_t sb = smem_u32(smr);
    const int tid  = threadIdx.x;
    const int wid  = tid >> 5;
    const int lane = tid & 31;
    const int wr = wid >> 2;         // 0..1
    const int wc = wid & 3;          // 0..3
    const int m0 = blockIdx.y * 128;
    const int n0 = blockIdx.x * 128;

    const __nv_bfloat16* Ah = Ahi + (size_t)m0 * DIM;
    const __nv_bfloat16* Al = Alo + (size_t)m0 * DIM;
    const __nv_bfloat16* Wh = Whi + (size_t)n0 * DIM;
    const __nv_bfloat16* Wl = Wlo + (size_t)n0 * DIM;

    float c[4][4][4];
    #pragma unroll
    for (int i = 0; i < 4; i++)
        #pragma unroll
        for (int j = 0; j < 4; j++)
            #pragma unroll
            for (int e = 0; e < 4; e++) c[i][j][e] = 0.f;

    // prologue: chunks 0..2
    #pragma unroll
    for (int p = 0; p < 3; p++) {
        // chunk p is always phase 0 (Ahi x Whi) since 3 < 32
        uint32_t st = sb + (uint32_t)p * STAGE_B;
        load_chunk(st, st + ATILE_B, Ah, Wh, p * 32, tid);
    }

    // precomputed ldmatrix lane addressing
    const uint32_t a_row = (uint32_t)(lane & 15);
    const uint32_t a_koff = (uint32_t)((lane >> 4) * 8);
    const uint32_t b_row = (uint32_t)(((lane >> 4) << 3) + (lane & 7));
    const uint32_t b_koff = (uint32_t)(((lane >> 3) & 1) * 8);

    for (int ch = 0; ch < NCHUNK; ch++) {
        cp_wait2();
        __syncthreads();

        const int nc = ch + 3;
        if (nc < NCHUNK) {
            const int ph = nc >> 5;
            const int kk = (nc & 31) * 32;
            const __nv_bfloat16* Ap = (ph == 1) ? Al : Ah;
            const __nv_bfloat16* Wp = (ph == 2) ? Wl : Wh;
            uint32_t st = sb + (uint32_t)(nc & 3) * STAGE_B;
            load_chunk(st, st + ATILE_B, Ap, Wp, kk, tid);
        } else {
            cp_commit();   // empty group keeps wait_group bookkeeping uniform
        }

        const uint32_t sA = sb + (uint32_t)(ch & 3) * STAGE_B;
        const uint32_t sW = sA + ATILE_B;

        #pragma unroll
        for (int h = 0; h < 2; h++) {
            uint32_t a[4][4], b[2][4];
            const uint32_t acol = (h * 16 + a_koff) * 2;
            const uint32_t bcol = (h * 16 + b_koff) * 2;
            #pragma unroll
            for (int i = 0; i < 4; i++)
                ldsm4(a[i], sA + (wr * 64 + i * 16 + a_row) * PADB + acol);
            #pragma unroll
            for (int jp = 0; jp < 2; jp++)
                ldsm4(b[jp], sW + (wc * 32 + jp * 16 + b_row) * PADB + bcol);
            #pragma unroll
            for (int i = 0; i < 4; i++) {
                mma16816(c[i][0], a[i], &b[0][0]);
                mma16816(c[i][1], a[i], &b[0][2]);
                mma16816(c[i][2], a[i], &b[1][0]);
                mma16816(c[i][3], a[i], &b[1][2]);
            }
        }
    }
    cp_wait0();

    // epilogue: bias + store
    const int g   = lane >> 2;
    const int tig = lane & 3;
    #pragma unroll
    for (int i = 0; i < 4; i++) {
        const int r0 = m0 + wr * 64 + i * 16 + g;
        #pragma unroll
        for (int j = 0; j < 4; j++) {
            const int cb = n0 + wc * 32 + j * 8 + 2 * tig;
            const float b0 = bias[cb], b1 = bias[cb + 1];
            float2 v0 = make_float2(c[i][j][0] + b0, c[i][j][1] + b1);
            float2 v1 = make_float2(c[i][j][2] + b0, c[i][j][3] + b1);
            *(float2*)(C + (size_t)r0 * DIM + cb)       = v0;
            *(float2*)(C + (size_t)(r0 + 8) * DIM + cb) = v1;
        }
    }
}

// ---------------------------------------------------------------------------
// Causal flash attention, fp32 (unchanged from round 1)
// ---------------------------------------------------------------------------
#define ATTN_SMEM ((64 * 64 + 64 * 64 + 128 * 65) * 4)

__global__ __launch_bounds__(128)
void attn_kernel(const float* __restrict__ Q, const float* __restrict__ K,
                 const float* __restrict__ V, float* __restrict__ O)
{
    extern __shared__ float sm[];
    float* Ks = sm;
    float* Vs = sm + 64 * 64;
    float* Ss = sm + 2 * 64 * 64;

    const int tid   = threadIdx.x;
    const int qtile = blockIdx.x;
    const int bh    = blockIdx.y;
    const int b     = bh >> 4;
    const int h     = bh & 15;

    const int sq = qtile * 128 + tid;
    const size_t rowm = (size_t)(b * SEQ + sq) * DIM + h * HDIM;

    __align__(16) float q[HDIM];
    __align__(16) float acc[HDIM];
    #pragma unroll
    for (int i = 0; i < 16; i++)
        ((float4*)q)[i] = ((const float4*)(Q + rowm))[i];
    #pragma unroll
    for (int d = 0; d < HDIM; d++) acc[d] = 0.f;

    float mi = -1e30f, li = 0.f;

    const float* Kbase = K + (size_t)b * SEQ * DIM + h * HDIM;
    const float* Vbase = V + (size_t)b * SEQ * DIM + h * HDIM;

    const int njt = 2 * qtile + 2;
    const int t   = tid >> 1;
    const int off = (tid & 1) * 32;

    for (int j = 0; j < njt; j++) {
        const float4* kg = (const float4*)(Kbase + (size_t)(j * 64 + t) * DIM + off);
        const float4* vg = (const float4*)(Vbase + (size_t)(j * 64 + t) * DIM + off);
        float4* kd = (float4*)(Ks + t * 64 + off);
        float4* vd = (float4*)(Vs + t * 64 + off);

        __syncthreads();
        #pragma unroll
        for (int i = 0; i < 8; i++) { kd[i] = kg[i]; vd[i] = vg[i]; }
        __syncthreads();

        float tmax = -1e30f;
        const int kidx0 = j * 64;
        #pragma unroll 4
        for (int t2 = 0; t2 < 64; t2++) {
            const float4* kr = (const float4*)(Ks + t2 * 64);
            float s0 = 0.f, s1 = 0.f, s2 = 0.f, s3 = 0.f;
            #pragma unroll
            for (int d = 0; d < 16; d++) {
                float4 k4 = kr[d];
                s0 = fmaf(q[4 * d + 0], k4.x, s0);
                s1 = fmaf(q[4 * d + 1], k4.y, s1);
                s2 = fmaf(q[4 * d + 2], k4.z, s2);
                s3 = fmaf(q[4 * d + 3], k4.w, s3);
            }
            float sc = ((s0 + s1) + (s2 + s3)) * 0.125f;
            if (kidx0 + t2 > sq) sc = -1e30f;
            tmax = fmaxf(tmax, sc);
            Ss[tid * 65 + t2] = sc;
        }

        const float mnew = fmaxf(mi, tmax);
        const float corr = __expf(mi - mnew);
        li *= corr;
        #pragma unroll
        for (int d = 0; d < HDIM; d++) acc[d] *= corr;

        #pragma unroll 2
        for (int t2 = 0; t2 < 64; t2++) {
            const float p = __expf(Ss[tid * 65 + t2] - mnew);
            li += p;
            const float4* vr = (const float4*)(Vs + t2 * 64);
            #pragma unroll
            for (int d = 0; d < 16; d++) {
                float4 v4 = vr[d];
                acc[4 * d + 0] = fmaf(p, v4.x, acc[4 * d + 0]);
                acc[4 * d + 1] = fmaf(p, v4.y, acc[4 * d + 1]);
                acc[4 * d + 2] = fmaf(p, v4.z, acc[4 * d + 2]);
                acc[4 * d + 3] = fmaf(p, v4.w, acc[4 * d + 3]);
            }
        }
        mi = mnew;
    }

    const float inv = 1.f / li;
    float* Op = O + rowm;
    #pragma unroll
    for (int d = 0; d < HDIM; d += 4) {
        float4 o4 = make_float4(acc[d] * inv, acc[d + 1] * inv,
                                acc[d + 2] * inv, acc[d + 3] * inv);
        *(float4*)(Op + d) = o4;
    }
}

// ---------------------------------------------------------------------------
// Launch
// ---------------------------------------------------------------------------
extern "C" void kernel_launch(void* const* d_in, const int* in_sizes, int n_in,
                              void* d_out, int out_size)
{
    const float* X  = (const float*)d_in[0];
    const float* Wq = (const float*)d_in[1];
    const float* bq = (const float*)d_in[2];
    const float* Wk = (const float*)d_in[3];
    const float* bk = (const float*)d_in[4];
    const float* Wv = (const float*)d_in[5];
    const float* bv = (const float*)d_in[6];
    const float* Wo = (const float*)d_in[7];
    const float* bo = (const float*)d_in[8];
    float* out = (float*)d_out;

    float *Q, *K, *V, *O;
    cudaGetSymbolAddress((void**)&Q, g_Q);
    cudaGetSymbolAddress((void**)&K, g_K);
    cudaGetSymbolAddress((void**)&V, g_V);
    cudaGetSymbolAddress((void**)&O, g_O);

    __nv_bfloat16 *Xhi, *Xlo, *Ohi, *Olo;
    __nv_bfloat16 *Wqh, *Wql, *Wkh, *Wkl, *Wvh, *Wvl, *Woh, *Wol;
    cudaGetSymbolAddress((void**)&Xhi, g_Xhi);
    cudaGetSymbolAddress((void**)&Xlo, g_Xlo);
    cudaGetSymbolAddress((void**)&Ohi, g_Ohi);
    cudaGetSymbolAddress((void**)&Olo, g_Olo);
    cudaGetSymbolAddress((void**)&Wqh, g_Wqhi);
    cudaGetSymbolAddress((void**)&Wql, g_Wqlo);
    cudaGetSymbolAddress((void**)&Wkh, g_Wkhi);
    cudaGetSymbolAddress((void**)&Wkl, g_Wklo);
    cudaGetSymbolAddress((void**)&Wvh, g_Wvhi);
    cudaGetSymbolAddress((void**)&Wvl, g_Wvlo);
    cudaGetSymbolAddress((void**)&Woh, g_Wohi);
    cudaGetSymbolAddress((void**)&Wol, g_Wolo);

    cudaFuncSetAttribute(gemm_tc, cudaFuncAttributeMaxDynamicSharedMemorySize, GEMM_SMEM);
    cudaFuncSetAttribute(attn_kernel, cudaFuncAttributeMaxDynamicSharedMemorySize, ATTN_SMEM);

    const int nX4 = MTOT * DIM / 4;      // 1048576
    const int nW4 = DIM * DIM / 4;       // 262144

    split_kernel<<<nX4 / 256, 256>>>((const float4*)X, (__nv_bfloat162*)Xhi,
                                     (__nv_bfloat162*)Xlo, nX4);
    split_kernel<<<nW4 / 256, 256>>>((const float4*)Wq, (__nv_bfloat162*)Wqh,
                                     (__nv_bfloat162*)Wql, nW4);
    split_kernel<<<nW4 / 256, 256>>>((const float4*)Wk, (__nv_bfloat162*)Wkh,
                                     (__nv_bfloat162*)Wkl, nW4);
    split_kernel<<<nW4 / 256, 256>>>((const float4*)Wv, (__nv_bfloat162*)Wvh,
                                     (__nv_bfloat162*)Wvl, nW4);
    split_kernel<<<nW4 / 256, 256>>>((const float4*)Wo, (__nv_bfloat162*)Woh,
                                     (__nv_bfloat162*)Wol, nW4);

    dim3 ggrid(DIM / 128, MTOT / 128);   // (8, 32)
    gemm_tc<<<ggrid, 256, GEMM_SMEM>>>(Xhi, Xlo, Wqh, Wql, bq, Q);
    gemm_tc<<<ggrid, 256, GEMM_SMEM>>>(Xhi, Xlo, Wkh, Wkl, bk, K);
    gemm_tc<<<ggrid, 256, GEMM_SMEM>>>(Xhi, Xlo, Wvh, Wvl, bv, V);

    attn_kernel<<<dim3(SEQ / 128, BATCH * NH), 128, ATTN_SMEM>>>(Q, K, V, O);

    split_kernel<<<nX4 / 256, 256>>>((const float4*)O, (__nv_bfloat162*)Ohi,
                                     (__nv_bfloat162*)Olo, nX4);
    gemm_tc<<<ggrid, 256, GEMM_SMEM>>>(Ohi, Olo, Woh, Wol, bo, out);
}

// round 4
// speedup vs baseline: 2.9676x; 2.2837x over previous
#include <cuda_runtime.h>
#include <cuda_bf16.h>
#include <cstdint>

#define BATCH 2
#define SEQ   2048
#define DIM   1024
#define NH    16
#define HDIM  64
#define MTOT  (BATCH * SEQ)   // 4096

// ---------------------------------------------------------------------------
// Scratch (allocation-free __device__ globals)
// ---------------------------------------------------------------------------
__device__ __align__(16) float g_QKV[(size_t)MTOT * 3 * DIM];   // packed Q|K|V fp32
__device__ __align__(16) float g_O[(size_t)MTOT * DIM];

__device__ __align__(16) __nv_bfloat16 g_Xhi[(size_t)MTOT * DIM];
__device__ __align__(16) __nv_bfloat16 g_Xlo[(size_t)MTOT * DIM];
__device__ __align__(16) __nv_bfloat16 g_Ohi[(size_t)MTOT * DIM];
__device__ __align__(16) __nv_bfloat16 g_Olo[(size_t)MTOT * DIM];
__device__ __align__(16) __nv_bfloat16 g_Wall_hi[(size_t)3 * DIM * DIM];
__device__ __align__(16) __nv_bfloat16 g_Wall_lo[(size_t)3 * DIM * DIM];
__device__ __align__(16) __nv_bfloat16 g_Wohi[(size_t)DIM * DIM];
__device__ __align__(16) __nv_bfloat16 g_Wolo[(size_t)DIM * DIM];
__device__ float g_bias[3 * DIM];

// attention operands, per-head layouts
__device__ __align__(16) __nv_bfloat16 g_Qh[(size_t)BATCH * NH * SEQ * HDIM];
__device__ __align__(16) __nv_bfloat16 g_Ql[(size_t)BATCH * NH * SEQ * HDIM];
__device__ __align__(16) __nv_bfloat16 g_Kh[(size_t)BATCH * NH * SEQ * HDIM];
__device__ __align__(16) __nv_bfloat16 g_Kl[(size_t)BATCH * NH * SEQ * HDIM];
__device__ __align__(16) __nv_bfloat16 g_Vth[(size_t)BATCH * NH * HDIM * SEQ];
__device__ __align__(16) __nv_bfloat16 g_Vtl[(size_t)BATCH * NH * HDIM * SEQ];

// ---------------------------------------------------------------------------
// PTX helpers (arch-neutral)
// ---------------------------------------------------------------------------
__device__ __forceinline__ uint32_t smem_u32(const void* p) {
    uint32_t a;
    asm("{ .reg .u64 t; cvta.to.shared.u64 t, %1; cvt.u32.u64 %0, t; }"
        : "=r"(a) : "l"(p));
    return a;
}
__device__ __forceinline__ void cp16(uint32_t dst, const void* src) {
    asm volatile("cp.async.cg.shared.global [%0], [%1], 16;" :: "r"(dst), "l"(src));
}
__device__ __forceinline__ void cp_commit() {
    asm volatile("cp.async.commit_group;" ::: "memory");
}
__device__ __forceinline__ void cp_wait0() {
    asm volatile("cp.async.wait_group 0;" ::: "memory");
}
__device__ __forceinline__ void cp_wait1() {
    asm volatile("cp.async.wait_group 1;" ::: "memory");
}
__device__ __forceinline__ void cp_wait2() {
    asm volatile("cp.async.wait_group 2;" ::: "memory");
}
__device__ __forceinline__ void ldsm4(uint32_t* r, uint32_t addr) {
    asm volatile("ldmatrix.sync.aligned.m8n8.x4.shared.b16 {%0,%1,%2,%3}, [%4];"
        : "=r"(r[0]), "=r"(r[1]), "=r"(r[2]), "=r"(r[3]) : "r"(addr));
}
__device__ __forceinline__ void mma16816(float* d, const uint32_t* a, const uint32_t* b) {
    asm volatile("mma.sync.aligned.m16n8k16.row.col.f32.bf16.bf16.f32 "
        "{%0,%1,%2,%3}, {%4,%5,%6,%7}, {%8,%9}, {%0,%1,%2,%3};"
        : "+f"(d[0]), "+f"(d[1]), "+f"(d[2]), "+f"(d[3])
        : "r"(a[0]), "r"(a[1]), "r"(a[2]), "r"(a[3]), "r"(b[0]), "r"(b[1]));
}

// x,y -> bf16 hi pair (packed u32) + bf16 residual pair
__device__ __forceinline__ void split2(float x, float y, uint32_t& hi, uint32_t& lo) {
    __nv_bfloat162 h = __floats2bfloat162_rn(x, y);
    float hx = __bfloat162float(__low2bfloat16(h));
    float hy = __bfloat162float(__high2bfloat16(h));
    __nv_bfloat162 l = __floats2bfloat162_rn(x - hx, y - hy);
    hi = *(uint32_t*)&h;
    lo = *(uint32_t*)&l;
}

// ---------------------------------------------------------------------------
// small prep kernels
// ---------------------------------------------------------------------------
__global__ __launch_bounds__(256)
void split_kernel(const float4* __restrict__ x, __nv_bfloat162* __restrict__ hi,
                  __nv_bfloat162* __restrict__ lo, int n4)
{
    int i = blockIdx.x * 256 + threadIdx.x;
    if (i >= n4) return;
    float4 v = x[i];
    uint32_t h0, l0, h1, l1;
    split2(v.x, v.y, h0, l0);
    split2(v.z, v.w, h1, l1);
    *(uint32_t*)&hi[2 * i]     = h0;
    *(uint32_t*)&hi[2 * i + 1] = h1;
    *(uint32_t*)&lo[2 * i]     = l0;
    *(uint32_t*)&lo[2 * i + 1] = l1;
}

__global__ __launch_bounds__(256)
void pack_bias(const float* __restrict__ bq, const float* __restrict__ bk,
               const float* __restrict__ bv, float* __restrict__ out)
{
    int i = blockIdx.x * 256 + threadIdx.x;
    if (i >= 3 * DIM) return;
    out[i] = (i < DIM) ? bq[i] : (i < 2 * DIM) ? bk[i - DIM] : bv[i - 2 * DIM];
}

// QKV[4096][3072] (fp32) -> per-head bf16 hi/lo [bh][s][64]
__global__ __launch_bounds__(256)
void qk_split(const float* __restrict__ QKV, int coloff,
              __nv_bfloat16* __restrict__ Oh, __nv_bfloat16* __restrict__ Ol)
{
    int idx = blockIdx.x * 256 + threadIdx.x;          // (bh, s, d4)
    int d4  = idx & 15;
    int s   = (idx >> 4) & 2047;
    int bh  = idx >> 15;
    int b = bh >> 4, h = bh & 15;
    float4 v = *(const float4*)(QKV + (size_t)(b * SEQ + s) * 3072
                                + coloff + h * HDIM + d4 * 4);
    uint32_t h0, l0, h1, l1;
    split2(v.x, v.y, h0, l0);
    split2(v.z, v.w, h1, l1);
    size_t o = ((size_t)bh * SEQ + s) * HDIM + d4 * 4;
    *(uint2*)(Oh + o) = make_uint2(h0, h1);
    *(uint2*)(Ol + o) = make_uint2(l0, l1);
}

// V columns of QKV -> Vt[bh][d][s] bf16 hi/lo (64x64 smem tile transpose)
__global__ __launch_bounds__(256)
void vt_split(const float* __restrict__ QKV,
              __nv_bfloat16* __restrict__ Vh, __nv_bfloat16* __restrict__ Vl)
{
    __shared__ float vs[64][65];
    const int tid = threadIdx.x;
    const int s0  = blockIdx.x * 64;
    const int bh  = blockIdx.y;
    const int b = bh >> 4, h = bh & 15;
    const float* base = QKV + (size_t)(b * SEQ + s0) * 3072 + 2 * DIM + h * HDIM;

    #pragma unroll
    for (int p = 0; p < 4; p++) {
        int r  = (tid >> 4) + p * 16;
        int c4 = tid & 15;
        float4 v = *(const float4*)(base + (size_t)r * 3072 + c4 * 4);
        vs[r][c4 * 4 + 0] = v.x;
        vs[r][c4 * 4 + 1] = v.y;
        vs[r][c4 * 4 + 2] = v.z;
        vs[r][c4 * 4 + 3] = v.w;
    }
    __syncthreads();

    const int d  = tid >> 2;
    const int sb = (tid & 3) * 16;
    __nv_bfloat16* oh = Vh + ((size_t)bh * HDIM + d) * SEQ + s0 + sb;
    __nv_bfloat16* ol = Vl + ((size_t)bh * HDIM + d) * SEQ + s0 + sb;
    #pragma unroll
    for (int i = 0; i < 8; i++) {
        uint32_t hi, lo;
        split2(vs[sb + 2 * i][d], vs[sb + 2 * i + 1][d], hi, lo);
        *(uint32_t*)(oh + 2 * i) = hi;
        *(uint32_t*)(ol + 2 * i) = lo;
    }
}

// ---------------------------------------------------------------------------
// bf16 split-GEMM via mma.sync (validated R3), now with ldc parameter
// C[M,ldc] = Ahi@Whi^T + Alo@Whi^T + Ahi@Wlo^T + bias ; K = 1024 (K'=3072)
// ---------------------------------------------------------------------------
#define PADB 80
#define ATILE_B (128 * PADB)
#define STAGE_B (2 * ATILE_B)
#define NSTAGE 4
#define GEMM_SMEM (NSTAGE * STAGE_B)
#define NCHUNK 96

__device__ __forceinline__ void load_chunk(uint32_t sA, uint32_t sW,
    const __nv_bfloat16* __restrict__ A, const __nv_bfloat16* __restrict__ W,
    int k0, int tid)
{
    const int r = tid >> 2;
    const int q = tid & 3;
    const uint32_t doff = (uint32_t)q * 16;
    const int goff = k0 + q * 8;
    cp16(sA + (uint32_t)r * PADB + doff,        A + (size_t)r * DIM + goff);
    cp16(sA + (uint32_t)(r + 64) * PADB + doff, A + (size_t)(r + 64) * DIM + goff);
    cp16(sW + (uint32_t)r * PADB + doff,        W + (size_t)r * DIM + goff);
    cp16(sW + (uint32_t)(r + 64) * PADB + doff, W + (size_t)(r + 64) * DIM + goff);
    cp_commit();
}

__global__ __launch_bounds__(256)
void gemm_tc(const __nv_bfloat16* __restrict__ Ahi, const __nv_bfloat16* __restrict__ Alo,
             const __nv_bfloat16* __restrict__ Whi, const __nv_bfloat16* __restrict__ Wlo,
             const float* __restrict__ bias, float* __restrict__ C, int ldc)
{
    extern __shared__ char smr[];
    const uint32_t sb = smem_u32(smr);
    const int tid  = threadIdx.x;
    const int wid  = tid >> 5;
    const int lane = tid & 31;
    const int wr = wid >> 2;
    const int wc = wid & 3;
    const int m0 = blockIdx.y * 128;
    const int n0 = blockIdx.x * 128;

    const __nv_bfloat16* Ah = Ahi + (size_t)m0 * DIM;
    const __nv_bfloat16* Al = Alo + (size_t)m0 * DIM;
    const __nv_bfloat16* Wh = Whi + (size_t)n0 * DIM;
    const __nv_bfloat16* Wl = Wlo + (size_t)n0 * DIM;

    float c[4][4][4];
    #pragma unroll
    for (int i = 0; i < 4; i++)
        #pragma unroll
        for (int j = 0; j < 4; j++)
            #pragma unroll
            for (int e = 0; e < 4; e++) c[i][j][e] = 0.f;

    #pragma unroll
    for (int p = 0; p < 3; p++) {
        uint32_t st = sb + (uint32_t)p * STAGE_B;
        load_chunk(st, st + ATILE_B, Ah, Wh, p * 32, tid);
    }

    const uint32_t a_row  = (uint32_t)(lane & 15);
    const uint32_t a_koff = (uint32_t)((lane >> 4) * 8);
    const uint32_t b_row  = (uint32_t)(((lane >> 4) << 3) + (lane & 7));
    const uint32_t b_koff = (uint32_t)(((lane >> 3) & 1) * 8);

    for (int ch = 0; ch < NCHUNK; ch++) {
        cp_wait2();
        __syncthreads();

        const int nc = ch + 3;
        if (nc < NCHUNK) {
            const int ph = nc >> 5;
            const int kk = (nc & 31) * 32;
            const __nv_bfloat16* Ap = (ph == 1) ? Al : Ah;
            const __nv_bfloat16* Wp = (ph == 2) ? Wl : Wh;
            uint32_t st = sb + (uint32_t)(nc & 3) * STAGE_B;
            load_chunk(st, st + ATILE_B, Ap, Wp, kk, tid);
        } else {
            cp_commit();
        }

        const uint32_t sA = sb + (uint32_t)(ch & 3) * STAGE_B;
        const uint32_t sW = sA + ATILE_B;

        #pragma unroll
        for (int h = 0; h < 2; h++) {
            uint32_t a[4][4], b[2][4];
            const uint32_t acol = (h * 16 + a_koff) * 2;
            const uint32_t bcol = (h * 16 + b_koff) * 2;
            #pragma unroll
            for (int i = 0; i < 4; i++)
                ldsm4(a[i], sA + (wr * 64 + i * 16 + a_row) * PADB + acol);
            #pragma unroll
            for (int jp = 0; jp < 2; jp++)
                ldsm4(b[jp], sW + (wc * 32 + jp * 16 + b_row) * PADB + bcol);
            #pragma unroll
            for (int i = 0; i < 4; i++) {
                mma16816(c[i][0], a[i], &b[0][0]);
                mma16816(c[i][1], a[i], &b[0][2]);
                mma16816(c[i][2], a[i], &b[1][0]);
                mma16816(c[i][3], a[i], &b[1][2]);
            }
        }
    }
    cp_wait0();

    const int g   = lane >> 2;
    const int tig = lane & 3;
    #pragma unroll
    for (int i = 0; i < 4; i++) {
        const int r0 = m0 + wr * 64 + i * 16 + g;
        #pragma unroll
        for (int j = 0; j < 4; j++) {
            const int cb = n0 + wc * 32 + j * 8 + 2 * tig;
            const float b0 = bias[cb], b1 = bias[cb + 1];
            float2 v0 = make_float2(c[i][j][0] + b0, c[i][j][1] + b1);
            float2 v1 = make_float2(c[i][j][2] + b0, c[i][j][3] + b1);
            *(float2*)(C + (size_t)r0 * ldc + cb)       = v0;
            *(float2*)(C + (size_t)(r0 + 8) * ldc + cb) = v1;
        }
    }
}

// ---------------------------------------------------------------------------
// Causal flash attention on HMMA, bf16 hi/lo split (3-product).
// grid (16, 32): x -> q-tile (reversed for heavy-first), y -> (b,h).
// 8 warps x 16 q-rows. K/V in 2-stage cp.async pipeline, V pre-transposed.
// ---------------------------------------------------------------------------
#define APAD 144
#define ATT_Q_BYTES (128 * APAD)            // 18432 per tensor
#define ATT_T_BYTES (64 * APAD)             // 9216 per tensor
#define ATT_STAGE   (4 * ATT_T_BYTES)       // Khi,Klo,Vhi,Vlo = 36864
#define ATT_SMEM    (2 * ATT_Q_BYTES + 2 * ATT_STAGE)   // 110592

__device__ __forceinline__ void load_kv(uint32_t dst,
    const __nv_bfloat16* __restrict__ Khp, const __nv_bfloat16* __restrict__ Klp,
    const __nv_bfloat16* __restrict__ Vhp, const __nv_bfloat16* __restrict__ Vlp,
    int j, int tid)
{
    const int r  = tid >> 2;
    const int c0 = tid & 3;
    const uint32_t ro = (uint32_t)r * APAD;
    const size_t kg = (size_t)(j * 64 + r) * HDIM;
    const size_t vg = (size_t)r * SEQ + j * 64;
    cp16(dst + ro + c0 * 16,                    Khp + kg + c0 * 8);
    cp16(dst + ro + (c0 + 4) * 16,              Khp + kg + (c0 + 4) * 8);
    cp16(dst + ATT_T_BYTES + ro + c0 * 16,       Klp + kg + c0 * 8);
    cp16(dst + ATT_T_BYTES + ro + (c0 + 4) * 16, Klp + kg + (c0 + 4) * 8);
    cp16(dst + 2 * ATT_T_BYTES + ro + c0 * 16,       Vhp + vg + c0 * 8);
    cp16(dst + 2 * ATT_T_BYTES + ro + (c0 + 4) * 16, Vhp + vg + (c0 + 4) * 8);
    cp16(dst + 3 * ATT_T_BYTES + ro + c0 * 16,       Vlp + vg + c0 * 8);
    cp16(dst + 3 * ATT_T_BYTES + ro + (c0 + 4) * 16, Vlp + vg + (c0 + 4) * 8);
    cp_commit();
}

__global__ __launch_bounds__(256)
void attn_mma(const __nv_bfloat16* __restrict__ Qh, const __nv_bfloat16* __restrict__ Ql,
              const __nv_bfloat16* __restrict__ Kh, const __nv_bfloat16* __restrict__ Kl,
              const __nv_bfloat16* __restrict__ Vth, const __nv_bfloat16* __restrict__ Vtl,
              float* __restrict__ O)
{
    extern __shared__ char smr[];
    const uint32_t sbse = smem_u32(smr);
    const uint32_t sQh = sbse;
    const uint32_t sQl = sbse + ATT_Q_BYTES;
    const uint32_t skv = sbse + 2 * ATT_Q_BYTES;

    const int tid  = threadIdx.x;
    const int w    = tid >> 5;
    const int lane = tid & 31;
    const int g    = lane >> 2;
    const int t    = lane & 3;
    const int qt   = 15 - blockIdx.x;     // heavy tiles first
    const int bh   = blockIdx.y;
    const int b    = bh >> 4;
    const int h    = bh & 15;

    const __nv_bfloat16* Qhp = Qh + ((size_t)bh * SEQ + qt * 128) * HDIM;
    const __nv_bfloat16* Qlp = Ql + ((size_t)bh * SEQ + qt * 128) * HDIM;
    const __nv_bfloat16* Khp = Kh + (size_t)bh * SEQ * HDIM;
    const __nv_bfloat16* Klp = Kl + (size_t)bh * SEQ * HDIM;
    const __nv_bfloat16* Vhp = Vth + (size_t)bh * HDIM * SEQ;
    const __nv_bfloat16* Vlp = Vtl + (size_t)bh * HDIM * SEQ;

    // Q tile -> smem (one group)
    #pragma unroll
    for (int i = 0; i < 4; i++) {
        int idx = tid + i * 256;
        int r = idx >> 3, q = idx & 7;
        cp16(sQh + (uint32_t)r * APAD + q * 16, Qhp + (size_t)r * HDIM + q * 8);
        cp16(sQl + (uint32_t)r * APAD + q * 16, Qlp + (size_t)r * HDIM + q * 8);
    }
    cp_commit();
    load_kv(skv, Khp, Klp, Vhp, Vlp, 0, tid);   // kv tile 0, second group
    cp_wait1();                                  // Q landed
    __syncthreads();

    const uint32_t a_row  = (uint32_t)(lane & 15);
    const uint32_t a_koff = (uint32_t)((lane >> 4) * 8);
    const uint32_t b_row  = (uint32_t)(((lane >> 4) << 3) + (lane & 7));
    const uint32_t b_koff = (uint32_t)(((lane >> 3) & 1) * 8);

    uint32_t qhi[4][4], qlo[4][4];
    #pragma unroll
    for (int h4 = 0; h4 < 4; h4++) {
        uint32_t col = (h4 * 16 + a_koff) * 2;
        ldsm4(qhi[h4], sQh + (w * 16 + a_row) * APAD + col);
        ldsm4(qlo[h4], sQl + (w * 16 + a_row) * APAD + col);
    }

    float o[8][4];
    #pragma unroll
    for (int nb = 0; nb < 8; nb++)
        #pragma unroll
        for (int e = 0; e < 4; e++) o[nb][e] = 0.f;
    float mi0 = -1e30f, mi1 = -1e30f, li0 = 0.f, li1 = 0.f;

    const int sq0 = qt * 128 + w * 16 + g;       // rows sq0 and sq0+8
    const int njt = 2 * qt + 2;
    const float CE = 0.125f * 1.4426950408889634f;

    for (int j = 0; j < njt; j++) {
        if (j + 1 < njt) load_kv(skv + ((j + 1) & 1) * ATT_STAGE,
                                 Khp, Klp, Vhp, Vlp, j + 1, tid);
        else             cp_commit();
        cp_wait1();
        __syncthreads();

        const uint32_t sK = skv + (j & 1) * ATT_STAGE;

        // --- scores ---
        float s[8][4];
        #pragma unroll
        for (int nb = 0; nb < 8; nb++)
            #pragma unroll
            for (int e = 0; e < 4; e++) s[nb][e] = 0.f;

        #pragma unroll
        for (int h4 = 0; h4 < 4; h4++) {
            const uint32_t col = (h4 * 16 + b_koff) * 2;
            #pragma unroll
            for (int jp = 0; jp < 4; jp++) {
                uint32_t kb[4], kl[4];
                ldsm4(kb, sK + (jp * 16 + b_row) * APAD + col);
                ldsm4(kl, sK + ATT_T_BYTES + (jp * 16 + b_row) * APAD + col);
                mma16816(s[2 * jp],     qhi[h4], kb);
                mma16816(s[2 * jp + 1], qhi[h4], kb + 2);
                mma16816(s[2 * jp],     qlo[h4], kb);
                mma16816(s[2 * jp + 1], qlo[h4], kb + 2);
                mma16816(s[2 * jp],     qhi[h4], kl);
                mma16816(s[2 * jp + 1], qhi[h4], kl + 2);
            }
        }

        // --- causal mask ---
        const int kb0 = j * 64 + 2 * t;
        #pragma unroll
        for (int nb = 0; nb < 8; nb++) {
            const int c0 = kb0 + nb * 8;
            if (c0     > sq0)     s[nb][0] = -1e30f;
            if (c0 + 1 > sq0)     s[nb][1] = -1e30f;
            if (c0     > sq0 + 8) s[nb][2] = -1e30f;
            if (c0 + 1 > sq0 + 8) s[nb][3] = -1e30f;
        }

        // --- online softmax ---
        float m0 = -1e30f, m1 = -1e30f;
        #pragma unroll
        for (int nb = 0; nb < 8; nb++) {
            m0 = fmaxf(m0, fmaxf(s[nb][0], s[nb][1]));
            m1 = fmaxf(m1, fmaxf(s[nb][2], s[nb][3]));
        }
        m0 = fmaxf(m0, __shfl_xor_sync(0xFFFFFFFFu, m0, 1));
        m0 = fmaxf(m0, __shfl_xor_sync(0xFFFFFFFFu, m0, 2));
        m1 = fmaxf(m1, __shfl_xor_sync(0xFFFFFFFFu, m1, 1));
        m1 = fmaxf(m1, __shfl_xor_sync(0xFFFFFFFFu, m1, 2));
        const float mn0 = fmaxf(mi0, m0), mn1 = fmaxf(mi1, m1);
        const float corr0 = exp2f((mi0 - mn0) * CE);
        const float corr1 = exp2f((mi1 - mn1) * CE);

        float rs0 = 0.f, rs1 = 0.f;
        #pragma unroll
        for (int nb = 0; nb < 8; nb++) {
            s[nb][0] = exp2f((s[nb][0] - mn0) * CE);
            s[nb][1] = exp2f((s[nb][1] - mn0) * CE);
            s[nb][2] = exp2f((s[nb][2] - mn1) * CE);
            s[nb][3] = exp2f((s[nb][3] - mn1) * CE);
            rs0 += s[nb][0] + s[nb][1];
            rs1 += s[nb][2] + s[nb][3];
        }
        rs0 += __shfl_xor_sync(0xFFFFFFFFu, rs0, 1);
        rs0 += __shfl_xor_sync(0xFFFFFFFFu, rs0, 2);
        rs1 += __shfl_xor_sync(0xFFFFFFFFu, rs1, 1);
        rs1 += __shfl_xor_sync(0xFFFFFFFFu, rs1, 2);
        li0 = li0 * corr0 + rs0;
        li1 = li1 * corr1 + rs1;
        mi0 = mn0; mi1 = mn1;

        #pragma unroll
        for (int nb = 0; nb < 8; nb++) {
            o[nb][0] *= corr0; o[nb][1] *= corr0;
            o[nb][2] *= corr1; o[nb][3] *= corr1;
        }

        // --- P fragments (C-layout -> A-layout, in-register) ---
        uint32_t phi[4][4], plo[4][4];
        #pragma unroll
        for (int h4 = 0; h4 < 4; h4++) {
            split2(s[2 * h4][0],     s[2 * h4][1],     phi[h4][0], plo[h4][0]);
            split2(s[2 * h4][2],     s[2 * h4][3],     phi[h4][1], plo[h4][1]);
            split2(s[2 * h4 + 1][0], s[2 * h4 + 1][1], phi[h4][2], plo[h4][2]);
            split2(s[2 * h4 + 1][2], s[2 * h4 + 1][3], phi[h4][3], plo[h4][3]);
        }

        // --- P @ V ---
        #pragma unroll
        for (int h4 = 0; h4 < 4; h4++) {
            const uint32_t col = (h4 * 16 + b_koff) * 2;
            #pragma unroll
            for (int jp = 0; jp < 4; jp++) {
                uint32_t vb[4], vl[4];
                ldsm4(vb, sK + 2 * ATT_T_BYTES + (jp * 16 + b_row) * APAD + col);
                ldsm4(vl, sK + 3 * ATT_T_BYTES + (jp * 16 + b_row) * APAD + col);
                mma16816(o[2 * jp],     phi[h4], vb);
                mma16816(o[2 * jp + 1], phi[h4], vb + 2);
                mma16816(o[2 * jp],     plo[h4], vb);
                mma16816(o[2 * jp + 1], plo[h4], vb + 2);
                mma16816(o[2 * jp],     phi[h4], vl);
                mma16816(o[2 * jp + 1], phi[h4], vl + 2);
            }
        }
        __syncthreads();
    }

    const float inv0 = 1.f / li0;
    const float inv1 = 1.f / li1;
    float* O0 = O + (size_t)(b * SEQ + sq0) * DIM + h * HDIM;
    float* O1 = O0 + (size_t)8 * DIM;
    #pragma unroll
    for (int nb = 0; nb < 8; nb++) {
        const int d = nb * 8 + 2 * t;
        *(float2*)(O0 + d) = make_float2(o[nb][0] * inv0, o[nb][1] * inv0);
        *(float2*)(O1 + d) = make_float2(o[nb][2] * inv1, o[nb][3] * inv1);
    }
}

// ---------------------------------------------------------------------------
// Launch
// ---------------------------------------------------------------------------
extern "C" void kernel_launch(void* const* d_in, const int* in_sizes, int n_in,
                              void* d_out, int out_size)
{
    const float* X  = (const float*)d_in[0];
    const float* Wq = (const float*)d_in[1];
    const float* bq = (const float*)d_in[2];
    const float* Wk = (const float*)d_in[3];
    const float* bk = (const float*)d_in[4];
    const float* Wv = (const float*)d_in[5];
    const float* bv = (const float*)d_in[6];
    const float* Wo = (const float*)d_in[7];
    const float* bo = (const float*)d_in[8];
    float* out = (float*)d_out;

    float *QKV, *O, *bias;
    cudaGetSymbolAddress((void**)&QKV, g_QKV);
    cudaGetSymbolAddress((void**)&O, g_O);
    cudaGetSymbolAddress((void**)&bias, g_bias);

    __nv_bfloat16 *Xhi, *Xlo, *Ohi, *Olo, *Wah, *Wal, *Woh, *Wol;
    __nv_bfloat16 *Qh, *Ql, *Kh, *Kl, *Vth, *Vtl;
    cudaGetSymbolAddress((void**)&Xhi, g_Xhi);
    cudaGetSymbolAddress((void**)&Xlo, g_Xlo);
    cudaGetSymbolAddress((void**)&Ohi, g_Ohi);
    cudaGetSymbolAddress((void**)&Olo, g_Olo);
    cudaGetSymbolAddress((void**)&Wah, g_Wall_hi);
    cudaGetSymbolAddress((void**)&Wal, g_Wall_lo);
    cudaGetSymbolAddress((void**)&Woh, g_Wohi);
    cudaGetSymbolAddress((void**)&Wol, g_Wolo);
    cudaGetSymbolAddress((void**)&Qh, g_Qh);
    cudaGetSymbolAddress((void**)&Ql, g_Ql);
    cudaGetSymbolAddress((void**)&Kh, g_Kh);
    cudaGetSymbolAddress((void**)&Kl, g_Kl);
    cudaGetSymbolAddress((void**)&Vth, g_Vth);
    cudaGetSymbolAddress((void**)&Vtl, g_Vtl);

    cudaFuncSetAttribute(gemm_tc, cudaFuncAttributeMaxDynamicSharedMemorySize, GEMM_SMEM);
    cudaFuncSetAttribute(attn_mma, cudaFuncAttributeMaxDynamicSharedMemorySize, ATT_SMEM);

    const int nX4 = MTOT * DIM / 4;
    const int nW4 = DIM * DIM / 4;
    const size_t W1 = (size_t)DIM * DIM;

    pack_bias<<<12, 256>>>(bq, bk, bv, bias);
    split_kernel<<<nX4 / 256, 256>>>((const float4*)X, (__nv_bfloat162*)Xhi,
                                     (__nv_bfloat162*)Xlo, nX4);
    split_kernel<<<nW4 / 256, 256>>>((const float4*)Wq, (__nv_bfloat162*)Wah,
                                     (__nv_bfloat162*)Wal, nW4);
    split_kernel<<<nW4 / 256, 256>>>((const float4*)Wk, (__nv_bfloat162*)(Wah + W1),
                                     (__nv_bfloat162*)(Wal + W1), nW4);
    split_kernel<<<nW4 / 256, 256>>>((const float4*)Wv, (__nv_bfloat162*)(Wah + 2 * W1),
                                     (__nv_bfloat162*)(Wal + 2 * W1), nW4);
    split_kernel<<<nW4 / 256, 256>>>((const float4*)Wo, (__nv_bfloat162*)Woh,
                                     (__nv_bfloat162*)Wol, nW4);

    // fused QKV projection: C[4096, 3072]
    gemm_tc<<<dim3(3 * DIM / 128, MTOT / 128), 256, GEMM_SMEM>>>(
        Xhi, Xlo, Wah, Wal, bias, QKV, 3 * DIM);

    // per-head bf16 operands
    qk_split<<<4096, 256>>>(QKV, 0,       Qh, Ql);
    qk_split<<<4096, 256>>>(QKV, DIM,     Kh, Kl);
    vt_split<<<dim3(SEQ / 64, BATCH * NH), 256>>>(QKV, Vth, Vtl);

    attn_mma<<<dim3(SEQ / 128, BATCH * NH), 256, ATT_SMEM>>>(Qh, Ql, Kh, Kl, Vth, Vtl, O);

    split_kernel<<<nX4 / 256, 256>>>((const float4*)O, (__nv_bfloat162*)Ohi,
                                     (__nv_bfloat162*)Olo, nX4);
    gemm_tc<<<dim3(DIM / 128, MTOT / 128), 256, GEMM_SMEM>>>(
        Ohi, Olo, Woh, Wol, bo, out, DIM);
}

// round 5
// speedup vs baseline: 3.0967x; 1.0435x over previous
#include <cuda_runtime.h>
#include <cuda_bf16.h>
#include <cstdint>

#define BATCH 2
#define SEQ   2048
#define DIM   1024
#define NH    16
#define HDIM  64
#define MTOT  (BATCH * SEQ)   // 4096

// ---------------------------------------------------------------------------
// Scratch (allocation-free __device__ globals)
// ---------------------------------------------------------------------------
__device__ __align__(16) __nv_bfloat16 g_Xhi[(size_t)MTOT * DIM];
__device__ __align__(16) __nv_bfloat16 g_Xlo[(size_t)MTOT * DIM];
__device__ __align__(16) __nv_bfloat16 g_Ohi[(size_t)MTOT * DIM];
__device__ __align__(16) __nv_bfloat16 g_Olo[(size_t)MTOT * DIM];
__device__ __align__(16) __nv_bfloat16 g_Wall_hi[(size_t)3 * DIM * DIM];
__device__ __align__(16) __nv_bfloat16 g_Wall_lo[(size_t)3 * DIM * DIM];
__device__ __align__(16) __nv_bfloat16 g_Wohi[(size_t)DIM * DIM];
__device__ __align__(16) __nv_bfloat16 g_Wolo[(size_t)DIM * DIM];
__device__ float g_bias[3 * DIM];

// attention operands, per-head layouts
__device__ __align__(16) __nv_bfloat16 g_Qh[(size_t)BATCH * NH * SEQ * HDIM];
__device__ __align__(16) __nv_bfloat16 g_Ql[(size_t)BATCH * NH * SEQ * HDIM];
__device__ __align__(16) __nv_bfloat16 g_Kh[(size_t)BATCH * NH * SEQ * HDIM];
__device__ __align__(16) __nv_bfloat16 g_Kl[(size_t)BATCH * NH * SEQ * HDIM];
__device__ __align__(16) __nv_bfloat16 g_Vth[(size_t)BATCH * NH * HDIM * SEQ];
__device__ __align__(16) __nv_bfloat16 g_Vtl[(size_t)BATCH * NH * HDIM * SEQ];

// ---------------------------------------------------------------------------
// PTX helpers (arch-neutral)
// ---------------------------------------------------------------------------
__device__ __forceinline__ uint32_t smem_u32(const void* p) {
    uint32_t a;
    asm("{ .reg .u64 t; cvta.to.shared.u64 t, %1; cvt.u32.u64 %0, t; }"
        : "=r"(a) : "l"(p));
    return a;
}
__device__ __forceinline__ void cp16(uint32_t dst, const void* src) {
    asm volatile("cp.async.cg.shared.global [%0], [%1], 16;" :: "r"(dst), "l"(src));
}
__device__ __forceinline__ void cp_commit() {
    asm volatile("cp.async.commit_group;" ::: "memory");
}
__device__ __forceinline__ void cp_wait0() {
    asm volatile("cp.async.wait_group 0;" ::: "memory");
}
__device__ __forceinline__ void cp_wait1() {
    asm volatile("cp.async.wait_group 1;" ::: "memory");
}
__device__ __forceinline__ void cp_wait2() {
    asm volatile("cp.async.wait_group 2;" ::: "memory");
}
__device__ __forceinline__ void ldsm4(uint32_t* r, uint32_t addr) {
    asm volatile("ldmatrix.sync.aligned.m8n8.x4.shared.b16 {%0,%1,%2,%3}, [%4];"
        : "=r"(r[0]), "=r"(r[1]), "=r"(r[2]), "=r"(r[3]) : "r"(addr));
}
__device__ __forceinline__ void mma16816(float* d, const uint32_t* a, const uint32_t* b) {
    asm volatile("mma.sync.aligned.m16n8k16.row.col.f32.bf16.bf16.f32 "
        "{%0,%1,%2,%3}, {%4,%5,%6,%7}, {%8,%9}, {%0,%1,%2,%3};"
        : "+f"(d[0]), "+f"(d[1]), "+f"(d[2]), "+f"(d[3])
        : "r"(a[0]), "r"(a[1]), "r"(a[2]), "r"(a[3]), "r"(b[0]), "r"(b[1]));
}

// x,y -> bf16 hi pair (packed u32) + bf16 residual pair
__device__ __forceinline__ void split2(float x, float y, uint32_t& hi, uint32_t& lo) {
    __nv_bfloat162 h = __floats2bfloat162_rn(x, y);
    float hx = __bfloat162float(__low2bfloat16(h));
    float hy = __bfloat162float(__high2bfloat16(h));
    __nv_bfloat162 l = __floats2bfloat162_rn(x - hx, y - hy);
    hi = *(uint32_t*)&h;
    lo = *(uint32_t*)&l;
}

// ---------------------------------------------------------------------------
// small prep kernels
// ---------------------------------------------------------------------------
__global__ __launch_bounds__(256)
void split_kernel(const float4* __restrict__ x, __nv_bfloat162* __restrict__ hi,
                  __nv_bfloat162* __restrict__ lo, int n4)
{
    int i = blockIdx.x * 256 + threadIdx.x;
    if (i >= n4) return;
    float4 v = x[i];
    uint32_t h0, l0, h1, l1;
    split2(v.x, v.y, h0, l0);
    split2(v.z, v.w, h1, l1);
    *(uint32_t*)&hi[2 * i]     = h0;
    *(uint32_t*)&hi[2 * i + 1] = h1;
    *(uint32_t*)&lo[2 * i]     = l0;
    *(uint32_t*)&lo[2 * i + 1] = l1;
}

__global__ __launch_bounds__(256)
void pack_bias(const float* __restrict__ bq, const float* __restrict__ bk,
               const float* __restrict__ bv, float* __restrict__ out)
{
    int i = blockIdx.x * 256 + threadIdx.x;
    if (i >= 3 * DIM) return;
    out[i] = (i < DIM) ? bq[i] : (i < 2 * DIM) ? bk[i - DIM] : bv[i - 2 * DIM];
}

// ---------------------------------------------------------------------------
// bf16 split-GEMM via mma.sync.
// MODE 0: C[M,DIM] fp32 = A@W^T + bias
// MODE 1: QKV projection; epilogue scatters per-head bf16 hi/lo:
//         Q,K -> [bh][s][64] ; V -> transposed [bh][d][s]
// K = 1024 folded to K' = 3072 (hi*hi, lo*hi, hi*lo). 2 CTAs/SM.
// ---------------------------------------------------------------------------
#define PADB 80
#define ATILE_B (128 * PADB)
#define STAGE_B (2 * ATILE_B)
#define NSTAGE 4
#define GEMM_SMEM (NSTAGE * STAGE_B)
#define NCHUNK 96

__device__ __forceinline__ void load_chunk(uint32_t sA, uint32_t sW,
    const __nv_bfloat16* __restrict__ A, const __nv_bfloat16* __restrict__ W,
    int k0, int tid)
{
    const int r = tid >> 2;
    const int q = tid & 3;
    const uint32_t doff = (uint32_t)q * 16;
    const int goff = k0 + q * 8;
    cp16(sA + (uint32_t)r * PADB + doff,        A + (size_t)r * DIM + goff);
    cp16(sA + (uint32_t)(r + 64) * PADB + doff, A + (size_t)(r + 64) * DIM + goff);
    cp16(sW + (uint32_t)r * PADB + doff,        W + (size_t)r * DIM + goff);
    cp16(sW + (uint32_t)(r + 64) * PADB + doff, W + (size_t)(r + 64) * DIM + goff);
    cp_commit();
}

template <int MODE>
__global__ __launch_bounds__(256, 2)
void gemm_tc(const __nv_bfloat16* __restrict__ Ahi, const __nv_bfloat16* __restrict__ Alo,
             const __nv_bfloat16* __restrict__ Whi, const __nv_bfloat16* __restrict__ Wlo,
             const float* __restrict__ bias, float* __restrict__ C,
             __nv_bfloat16* __restrict__ Qh, __nv_bfloat16* __restrict__ Ql,
             __nv_bfloat16* __restrict__ Kh, __nv_bfloat16* __restrict__ Kl,
             __nv_bfloat16* __restrict__ Vth, __nv_bfloat16* __restrict__ Vtl)
{
    extern __shared__ char smr[];
    const uint32_t sb = smem_u32(smr);
    const int tid  = threadIdx.x;
    const int wid  = tid >> 5;
    const int lane = tid & 31;
    const int wr = wid >> 2;
    const int wc = wid & 3;
    const int m0 = blockIdx.y * 128;
    const int n0 = blockIdx.x * 128;

    const __nv_bfloat16* Ah = Ahi + (size_t)m0 * DIM;
    const __nv_bfloat16* Al = Alo + (size_t)m0 * DIM;
    const __nv_bfloat16* Wh = Whi + (size_t)n0 * DIM;
    const __nv_bfloat16* Wl = Wlo + (size_t)n0 * DIM;

    float c[4][4][4];
    #pragma unroll
    for (int i = 0; i < 4; i++)
        #pragma unroll
        for (int j = 0; j < 4; j++)
            #pragma unroll
            for (int e = 0; e < 4; e++) c[i][j][e] = 0.f;

    #pragma unroll
    for (int p = 0; p < 3; p++) {
        uint32_t st = sb + (uint32_t)p * STAGE_B;
        load_chunk(st, st + ATILE_B, Ah, Wh, p * 32, tid);
    }

    const uint32_t a_row  = (uint32_t)(lane & 15);
    const uint32_t a_koff = (uint32_t)((lane >> 4) * 8);
    const uint32_t b_row  = (uint32_t)(((lane >> 4) << 3) + (lane & 7));
    const uint32_t b_koff = (uint32_t)(((lane >> 3) & 1) * 8);

    for (int ch = 0; ch < NCHUNK; ch++) {
        cp_wait2();
        __syncthreads();

        const int nc = ch + 3;
        if (nc < NCHUNK) {
            const int ph = nc >> 5;
            const int kk = (nc & 31) * 32;
            const __nv_bfloat16* Ap = (ph == 1) ? Al : Ah;
            const __nv_bfloat16* Wp = (ph == 2) ? Wl : Wh;
            uint32_t st = sb + (uint32_t)(nc & 3) * STAGE_B;
            load_chunk(st, st + ATILE_B, Ap, Wp, kk, tid);
        } else {
            cp_commit();
        }

        const uint32_t sA = sb + (uint32_t)(ch & 3) * STAGE_B;
        const uint32_t sW = sA + ATILE_B;

        #pragma unroll
        for (int h = 0; h < 2; h++) {
            uint32_t a[4][4], b[2][4];
            const uint32_t acol = (h * 16 + a_koff) * 2;
            const uint32_t bcol = (h * 16 + b_koff) * 2;
            #pragma unroll
            for (int i = 0; i < 4; i++)
                ldsm4(a[i], sA + (wr * 64 + i * 16 + a_row) * PADB + acol);
            #pragma unroll
            for (int jp = 0; jp < 2; jp++)
                ldsm4(b[jp], sW + (wc * 32 + jp * 16 + b_row) * PADB + bcol);
            #pragma unroll
            for (int i = 0; i < 4; i++) {
                mma16816(c[i][0], a[i], &b[0][0]);
                mma16816(c[i][1], a[i], &b[0][2]);
                mma16816(c[i][2], a[i], &b[1][0]);
                mma16816(c[i][3], a[i], &b[1][2]);
            }
        }
    }
    cp_wait0();

    const int g   = lane >> 2;
    const int tig = lane & 3;

    if (MODE == 0) {
        #pragma unroll
        for (int i = 0; i < 4; i++) {
            const int r0 = m0 + wr * 64 + i * 16 + g;
            #pragma unroll
            for (int j = 0; j < 4; j++) {
                const int cb = n0 + wc * 32 + j * 8 + 2 * tig;
                const float b0 = bias[cb], b1 = bias[cb + 1];
                float2 v0 = make_float2(c[i][j][0] + b0, c[i][j][1] + b1);
                float2 v1 = make_float2(c[i][j][2] + b0, c[i][j][3] + b1);
                *(float2*)(C + (size_t)r0 * DIM + cb)       = v0;
                *(float2*)(C + (size_t)(r0 + 8) * DIM + cb) = v1;
            }
        }
    } else {
        const int sec = n0 >> 10;            // 0=Q, 1=K, 2=V
        const int b   = m0 >> 11;            // batch (m0 is 128-aligned within 2048)
        const int sb0 = (m0 & 2047) + wr * 64 + g;
        #pragma unroll
        for (int i = 0; i < 4; i++) {
            const int s = sb0 + i * 16;      // rows s and s+8
            #pragma unroll
            for (int j = 0; j < 4; j++) {
                const int col = n0 + wc * 32 + j * 8 + 2 * tig;
                const int lc  = col & 1023;
                const int h   = lc >> 6;
                const int d   = lc & 63;
                const int bh  = b * NH + h;
                const float b0 = bias[col], b1 = bias[col + 1];
                const float v00 = c[i][j][0] + b0, v01 = c[i][j][1] + b1;
                const float v10 = c[i][j][2] + b0, v11 = c[i][j][3] + b1;
                if (sec < 2) {
                    __nv_bfloat16* Dh = (sec == 0) ? Qh : Kh;
                    __nv_bfloat16* Dl = (sec == 0) ? Ql : Kl;
                    uint32_t h0, l0, h1, l1;
                    split2(v00, v01, h0, l0);
                    split2(v10, v11, h1, l1);
                    const size_t o0 = ((size_t)bh * SEQ + s) * HDIM + d;
                    *(uint32_t*)(Dh + o0)              = h0;
                    *(uint32_t*)(Dl + o0)              = l0;
                    *(uint32_t*)(Dh + o0 + 8 * HDIM)   = h1;
                    *(uint32_t*)(Dl + o0 + 8 * HDIM)   = l1;
                } else {
                    const size_t vb0 = ((size_t)bh * HDIM + d) * SEQ + s;
                    const size_t vb1 = vb0 + SEQ;    // d+1
                    __nv_bfloat16 h00 = __float2bfloat16_rn(v00);
                    __nv_bfloat16 h01 = __float2bfloat16_rn(v01);
                    __nv_bfloat16 h10 = __float2bfloat16_rn(v10);
                    __nv_bfloat16 h11 = __float2bfloat16_rn(v11);
                    Vth[vb0]     = h00;
                    Vth[vb1]     = h01;
                    Vth[vb0 + 8] = h10;
                    Vth[vb1 + 8] = h11;
                    Vtl[vb0]     = __float2bfloat16_rn(v00 - __bfloat162float(h00));
                    Vtl[vb1]     = __float2bfloat16_rn(v01 - __bfloat162float(h01));
                    Vtl[vb0 + 8] = __float2bfloat16_rn(v10 - __bfloat162float(h10));
                    Vtl[vb1 + 8] = __float2bfloat16_rn(v11 - __bfloat162float(h11));
                }
            }
        }
    }
}

// ---------------------------------------------------------------------------
// Causal flash attention on HMMA, bf16 hi/lo split (3-product).
// Writes bf16 hi/lo output directly (feeds the output projection).
// ---------------------------------------------------------------------------
#define APAD 144
#define ATT_Q_BYTES (128 * APAD)
#define ATT_T_BYTES (64 * APAD)
#define ATT_STAGE   (4 * ATT_T_BYTES)
#define ATT_SMEM    (2 * ATT_Q_BYTES + 2 * ATT_STAGE)   // 110592

__device__ __forceinline__ void load_kv(uint32_t dst,
    const __nv_bfloat16* __restrict__ Khp, const __nv_bfloat16* __restrict__ Klp,
    const __nv_bfloat16* __restrict__ Vhp, const __nv_bfloat16* __restrict__ Vlp,
    int j, int tid)
{
    const int r  = tid >> 2;
    const int c0 = tid & 3;
    const uint32_t ro = (uint32_t)r * APAD;
    const size_t kg = (size_t)(j * 64 + r) * HDIM;
    const size_t vg = (size_t)r * SEQ + j * 64;
    cp16(dst + ro + c0 * 16,                    Khp + kg + c0 * 8);
    cp16(dst + ro + (c0 + 4) * 16,              Khp + kg + (c0 + 4) * 8);
    cp16(dst + ATT_T_BYTES + ro + c0 * 16,       Klp + kg + c0 * 8);
    cp16(dst + ATT_T_BYTES + ro + (c0 + 4) * 16, Klp + kg + (c0 + 4) * 8);
    cp16(dst + 2 * ATT_T_BYTES + ro + c0 * 16,       Vhp + vg + c0 * 8);
    cp16(dst + 2 * ATT_T_BYTES + ro + (c0 + 4) * 16, Vhp + vg + (c0 + 4) * 8);
    cp16(dst + 3 * ATT_T_BYTES + ro + c0 * 16,       Vlp + vg + c0 * 8);
    cp16(dst + 3 * ATT_T_BYTES + ro + (c0 + 4) * 16, Vlp + vg + (c0 + 4) * 8);
    cp_commit();
}

__global__ __launch_bounds__(256)
void attn_mma(const __nv_bfloat16* __restrict__ Qh, const __nv_bfloat16* __restrict__ Ql,
              const __nv_bfloat16* __restrict__ Kh, const __nv_bfloat16* __restrict__ Kl,
              const __nv_bfloat16* __restrict__ Vth, const __nv_bfloat16* __restrict__ Vtl,
              __nv_bfloat16* __restrict__ Ohi, __nv_bfloat16* __restrict__ Olo)
{
    extern __shared__ char smr[];
    const uint32_t sbse = smem_u32(smr);
    const uint32_t sQh = sbse;
    const uint32_t sQl = sbse + ATT_Q_BYTES;
    const uint32_t skv = sbse + 2 * ATT_Q_BYTES;

    const int tid  = threadIdx.x;
    const int w    = tid >> 5;
    const int lane = tid & 31;
    const int g    = lane >> 2;
    const int t    = lane & 3;
    const int qt   = 15 - blockIdx.x;
    const int bh   = blockIdx.y;
    const int b    = bh >> 4;
    const int h    = bh & 15;

    const __nv_bfloat16* Qhp = Qh + ((size_t)bh * SEQ + qt * 128) * HDIM;
    const __nv_bfloat16* Qlp = Ql + ((size_t)bh * SEQ + qt * 128) * HDIM;
    const __nv_bfloat16* Khp = Kh + (size_t)bh * SEQ * HDIM;
    const __nv_bfloat16* Klp = Kl + (size_t)bh * SEQ * HDIM;
    const __nv_bfloat16* Vhp = Vth + (size_t)bh * HDIM * SEQ;
    const __nv_bfloat16* Vlp = Vtl + (size_t)bh * HDIM * SEQ;

    #pragma unroll
    for (int i = 0; i < 4; i++) {
        int idx = tid + i * 256;
        int r = idx >> 3, q = idx & 7;
        cp16(sQh + (uint32_t)r * APAD + q * 16, Qhp + (size_t)r * HDIM + q * 8);
        cp16(sQl + (uint32_t)r * APAD + q * 16, Qlp + (size_t)r * HDIM + q * 8);
    }
    cp_commit();
    load_kv(skv, Khp, Klp, Vhp, Vlp, 0, tid);
    cp_wait1();
    __syncthreads();

    const uint32_t a_row  = (uint32_t)(lane & 15);
    const uint32_t a_koff = (uint32_t)((lane >> 4) * 8);
    const uint32_t b_row  = (uint32_t)(((lane >> 4) << 3) + (lane & 7));
    const uint32_t b_koff = (uint32_t)(((lane >> 3) & 1) * 8);

    uint32_t qhi[4][4], qlo[4][4];
    #pragma unroll
    for (int h4 = 0; h4 < 4; h4++) {
        uint32_t col = (h4 * 16 + a_koff) * 2;
        ldsm4(qhi[h4], sQh + (w * 16 + a_row) * APAD + col);
        ldsm4(qlo[h4], sQl + (w * 16 + a_row) * APAD + col);
    }

    float o[8][4];
    #pragma unroll
    for (int nb = 0; nb < 8; nb++)
        #pragma unroll
        for (int e = 0; e < 4; e++) o[nb][e] = 0.f;
    float mi0 = -1e30f, mi1 = -1e30f, li0 = 0.f, li1 = 0.f;

    const int sq0 = qt * 128 + w * 16 + g;
    const int njt = 2 * qt + 2;
    const float CE = 0.125f * 1.4426950408889634f;

    for (int j = 0; j < njt; j++) {
        if (j + 1 < njt) load_kv(skv + ((j + 1) & 1) * ATT_STAGE,
                                 Khp, Klp, Vhp, Vlp, j + 1, tid);
        else             cp_commit();
        cp_wait1();
        __syncthreads();

        const uint32_t sK = skv + (j & 1) * ATT_STAGE;

        float s[8][4];
        #pragma unroll
        for (int nb = 0; nb < 8; nb++)
            #pragma unroll
            for (int e = 0; e < 4; e++) s[nb][e] = 0.f;

        #pragma unroll
        for (int h4 = 0; h4 < 4; h4++) {
            const uint32_t col = (h4 * 16 + b_koff) * 2;
            #pragma unroll
            for (int jp = 0; jp < 4; jp++) {
                uint32_t kb[4], kl[4];
                ldsm4(kb, sK + (jp * 16 + b_row) * APAD + col);
                ldsm4(kl, sK + ATT_T_BYTES + (jp * 16 + b_row) * APAD + col);
                mma16816(s[2 * jp],     qhi[h4], kb);
                mma16816(s[2 * jp + 1], qhi[h4], kb + 2);
                mma16816(s[2 * jp],     qlo[h4], kb);
                mma16816(s[2 * jp + 1], qlo[h4], kb + 2);
                mma16816(s[2 * jp],     qhi[h4], kl);
                mma16816(s[2 * jp + 1], qhi[h4], kl + 2);
            }
        }

        const int kb0 = j * 64 + 2 * t;
        #pragma unroll
        for (int nb = 0; nb < 8; nb++) {
            const int c0 = kb0 + nb * 8;
            if (c0     > sq0)     s[nb][0] = -1e30f;
            if (c0 + 1 > sq0)     s[nb][1] = -1e30f;
            if (c0     > sq0 + 8) s[nb][2] = -1e30f;
            if (c0 + 1 > sq0 + 8) s[nb][3] = -1e30f;
        }

        float m0 = -1e30f, m1 = -1e30f;
        #pragma unroll
        for (int nb = 0; nb < 8; nb++) {
            m0 = fmaxf(m0, fmaxf(s[nb][0], s[nb][1]));
            m1 = fmaxf(m1, fmaxf(s[nb][2], s[nb][3]));
        }
        m0 = fmaxf(m0, __shfl_xor_sync(0xFFFFFFFFu, m0, 1));
        m0 = fmaxf(m0, __shfl_xor_sync(0xFFFFFFFFu, m0, 2));
        m1 = fmaxf(m1, __shfl_xor_sync(0xFFFFFFFFu, m1, 1));
        m1 = fmaxf(m1, __shfl_xor_sync(0xFFFFFFFFu, m1, 2));
        const float mn0 = fmaxf(mi0, m0), mn1 = fmaxf(mi1, m1);
        const float corr0 = exp2f((mi0 - mn0) * CE);
        const float corr1 = exp2f((mi1 - mn1) * CE);

        float rs0 = 0.f, rs1 = 0.f;
        #pragma unroll
        for (int nb = 0; nb < 8; nb++) {
            s[nb][0] = exp2f((s[nb][0] - mn0) * CE);
            s[nb][1] = exp2f((s[nb][1] - mn0) * CE);
            s[nb][2] = exp2f((s[nb][2] - mn1) * CE);
            s[nb][3] = exp2f((s[nb][3] - mn1) * CE);
            rs0 += s[nb][0] + s[nb][1];
            rs1 += s[nb][2] + s[nb][3];
        }
        rs0 += __shfl_xor_sync(0xFFFFFFFFu, rs0, 1);
        rs0 += __shfl_xor_sync(0xFFFFFFFFu, rs0, 2);
        rs1 += __shfl_xor_sync(0xFFFFFFFFu, rs1, 1);
        rs1 += __shfl_xor_sync(0xFFFFFFFFu, rs1, 2);
        li0 = li0 * corr0 + rs0;
        li1 = li1 * corr1 + rs1;
        mi0 = mn0; mi1 = mn1;

        #pragma unroll
        for (int nb = 0; nb < 8; nb++) {
            o[nb][0] *= corr0; o[nb][1] *= corr0;
            o[nb][2] *= corr1; o[nb][3] *= corr1;
        }

        uint32_t phi[4][4], plo[4][4];
        #pragma unroll
        for (int h4 = 0; h4 < 4; h4++) {
            split2(s[2 * h4][0],     s[2 * h4][1],     phi[h4][0], plo[h4][0]);
            split2(s[2 * h4][2],     s[2 * h4][3],     phi[h4][1], plo[h4][1]);
            split2(s[2 * h4 + 1][0], s[2 * h4 + 1][1], phi[h4][2], plo[h4][2]);
            split2(s[2 * h4 + 1][2], s[2 * h4 + 1][3], phi[h4][3], plo[h4][3]);
        }

        #pragma unroll
        for (int h4 = 0; h4 < 4; h4++) {
            const uint32_t col = (h4 * 16 + b_koff) * 2;
            #pragma unroll
            for (int jp = 0; jp < 4; jp++) {
                uint32_t vb[4], vl[4];
                ldsm4(vb, sK + 2 * ATT_T_BYTES + (jp * 16 + b_row) * APAD + col);
                ldsm4(vl, sK + 3 * ATT_T_BYTES + (jp * 16 + b_row) * APAD + col);
                mma16816(o[2 * jp],     phi[h4], vb);
                mma16816(o[2 * jp + 1], phi[h4], vb + 2);
                mma16816(o[2 * jp],     plo[h4], vb);
                mma16816(o[2 * jp + 1], plo[h4], vb + 2);
                mma16816(o[2 * jp],     phi[h4], vl);
                mma16816(o[2 * jp + 1], phi[h4], vl + 2);
            }
        }
        __syncthreads();
    }

    // epilogue: write bf16 hi/lo directly
    const float inv0 = 1.f / li0;
    const float inv1 = 1.f / li1;
    const size_t ob = (size_t)(b * SEQ + sq0) * DIM + h * HDIM;
    #pragma unroll
    for (int nb = 0; nb < 8; nb++) {
        const int d = nb * 8 + 2 * t;
        uint32_t h0, l0, h1, l1;
        split2(o[nb][0] * inv0, o[nb][1] * inv0, h0, l0);
        split2(o[nb][2] * inv1, o[nb][3] * inv1, h1, l1);
        *(uint32_t*)(Ohi + ob + d)           = h0;
        *(uint32_t*)(Olo + ob + d)           = l0;
        *(uint32_t*)(Ohi + ob + 8 * DIM + d) = h1;
        *(uint32_t*)(Olo + ob + 8 * DIM + d) = l1;
    }
}

// ---------------------------------------------------------------------------
// Launch.  Order matters for ncu (-s 5 -c 1): launch #6 = QKV gemm.
// ---------------------------------------------------------------------------
extern "C" void kernel_launch(void* const* d_in, const int* in_sizes, int n_in,
                              void* d_out, int out_size)
{
    const float* X  = (const float*)d_in[0];
    const float* Wq = (const float*)d_in[1];
    const float* bq = (const float*)d_in[2];
    const float* Wk = (const float*)d_in[3];
    const float* bk = (const float*)d_in[4];
    const float* Wv = (const float*)d_in[5];
    const float* bv = (const float*)d_in[6];
    const float* Wo = (const float*)d_in[7];
    const float* bo = (const float*)d_in[8];
    float* out = (float*)d_out;

    float* bias;
    cudaGetSymbolAddress((void**)&bias, g_bias);

    __nv_bfloat16 *Xhi, *Xlo, *Ohi, *Olo, *Wah, *Wal, *Woh, *Wol;
    __nv_bfloat16 *Qh, *Ql, *Kh, *Kl, *Vth, *Vtl;
    cudaGetSymbolAddress((void**)&Xhi, g_Xhi);
    cudaGetSymbolAddress((void**)&Xlo, g_Xlo);
    cudaGetSymbolAddress((void**)&Ohi, g_Ohi);
    cudaGetSymbolAddress((void**)&Olo, g_Olo);
    cudaGetSymbolAddress((void**)&Wah, g_Wall_hi);
    cudaGetSymbolAddress((void**)&Wal, g_Wall_lo);
    cudaGetSymbolAddress((void**)&Woh, g_Wohi);
    cudaGetSymbolAddress((void**)&Wol, g_Wolo);
    cudaGetSymbolAddress((void**)&Qh, g_Qh);
    cudaGetSymbolAddress((void**)&Ql, g_Ql);
    cudaGetSymbolAddress((void**)&Kh, g_Kh);
    cudaGetSymbolAddress((void**)&Kl, g_Kl);
    cudaGetSymbolAddress((void**)&Vth, g_Vth);
    cudaGetSymbolAddress((void**)&Vtl, g_Vtl);

    cudaFuncSetAttribute(gemm_tc<0>, cudaFuncAttributeMaxDynamicSharedMemorySize, GEMM_SMEM);
    cudaFuncSetAttribute(gemm_tc<1>, cudaFuncAttributeMaxDynamicSharedMemorySize, GEMM_SMEM);
    cudaFuncSetAttribute(attn_mma, cudaFuncAttributeMaxDynamicSharedMemorySize, ATT_SMEM);

    const int nX4 = MTOT * DIM / 4;
    const int nW4 = DIM * DIM / 4;
    const size_t W1 = (size_t)DIM * DIM;

    // launches 1-5
    pack_bias<<<12, 256>>>(bq, bk, bv, bias);
    split_kernel<<<nX4 / 256, 256>>>((const float4*)X, (__nv_bfloat162*)Xhi,
                                     (__nv_bfloat162*)Xlo, nX4);
    split_kernel<<<nW4 / 256, 256>>>((const float4*)Wq, (__nv_bfloat162*)Wah,
                                     (__nv_bfloat162*)Wal, nW4);
    split_kernel<<<nW4 / 256, 256>>>((const float4*)Wk, (__nv_bfloat162*)(Wah + W1),
                                     (__nv_bfloat162*)(Wal + W1), nW4);
    split_kernel<<<nW4 / 256, 256>>>((const float4*)Wv, (__nv_bfloat162*)(Wah + 2 * W1),
                                     (__nv_bfloat162*)(Wal + 2 * W1), nW4);

    // launch 6 (ncu-profiled): fused QKV projection with per-head split epilogue
    gemm_tc<1><<<dim3(3 * DIM / 128, MTOT / 128), 256, GEMM_SMEM>>>(
        Xhi, Xlo, Wah, Wal, bias, nullptr, Qh, Ql, Kh, Kl, Vth, Vtl);

    // launch 7: attention (writes Ohi/Olo)
    attn_mma<<<dim3(SEQ / 128, BATCH * NH), 256, ATT_SMEM>>>(
        Qh, Ql, Kh, Kl, Vth, Vtl, Ohi, Olo);

    // launches 8-9: Wo split + output projection
    split_kernel<<<nW4 / 256, 256>>>((const float4*)Wo, (__nv_bfloat162*)Woh,
                                     (__nv_bfloat162*)Wol, nW4);
    gemm_tc<0><<<dim3(DIM / 128, MTOT / 128), 256, GEMM_SMEM>>>(
        Ohi, Olo, Woh, Wol, bo, out,
        nullptr, nullptr, nullptr, nullptr, nullptr, nullptr);
}